// round 14
// baseline (speedup 1.0000x reference)
#include <cuda_runtime.h>
#include <cuda_fp16.h>
#include <cstdint>

#define B_    16384
#define CURD  2048
#define FEAT_ 2048
#define HEADS_ 16
#define HDIM  128

#define NTHREADS 128            // 4 warps, warp grid 2(M) x 2(N), warp tile 64x64
#define BM 128
#define BN 128
#define BK 64
#define A_STAGE   16384
#define STAGE_B   (2*A_STAGE)          // 32 KB
#define SMEM_BYTES (2*STAGE_B)         // 2 stages = 64 KB -> 2 CTAs/SM

// ---------------- scratch (device globals; no allocation allowed) ----------
__device__ __align__(16) __half g_xh [(size_t)B_*CURD];
__device__ __align__(16) __half g_v2h[(size_t)B_*FEAT_];
__device__ __align__(16) __half g_v3h[(size_t)B_*FEAT_];
__device__ __align__(16) __half g_wqh [(size_t)FEAT_*CURD];
__device__ __align__(16) __half g_wk2h[(size_t)FEAT_*FEAT_];
__device__ __align__(16) __half g_wv2h[(size_t)FEAT_*FEAT_];
__device__ __align__(16) __half g_wk3h[(size_t)FEAT_*FEAT_];
__device__ __align__(16) __half g_wv3h[(size_t)FEAT_*FEAT_];
__device__ __align__(16) __half g_woh [(size_t)CURD*FEAT_];
__device__ __align__(16) __half g_q  [(size_t)B_*FEAT_];
__device__ __align__(16) __half g_kv2[(size_t)B_*2*FEAT_];
__device__ __align__(16) __half g_kv3[(size_t)B_*2*FEAT_];
__device__ __align__(16) __half g_att[(size_t)B_*FEAT_];
__device__ __align__(16) float  g_y  [(size_t)B_*CURD];

// ---------------- helpers ----------------
__device__ __forceinline__ void cpa16(uint32_t s, const void* g) {
    asm volatile("cp.async.cg.shared.global [%0], [%1], 16;\n" :: "r"(s), "l"(g));
}

__device__ __forceinline__ void ldsm4(uint32_t* r, uint32_t addr) {
    asm volatile("ldmatrix.sync.aligned.m8n8.x4.shared.b16 {%0,%1,%2,%3}, [%4];"
        : "=r"(r[0]), "=r"(r[1]), "=r"(r[2]), "=r"(r[3]) : "r"(addr));
}

__device__ __forceinline__ void mma_f16(float* c, const uint32_t* a, const uint32_t* b) {
    asm volatile(
        "mma.sync.aligned.m16n8k16.row.col.f32.f16.f16.f32 "
        "{%0,%1,%2,%3}, {%4,%5,%6,%7}, {%8,%9}, {%0,%1,%2,%3};"
        : "+f"(c[0]), "+f"(c[1]), "+f"(c[2]), "+f"(c[3])
        : "r"(a[0]), "r"(a[1]), "r"(a[2]), "r"(a[3]),
          "r"(b[0]), "r"(b[1]));
}

// ---------------- fp32 -> fp16 conversions (merged launches) ----------------
__global__ void convA_kernel(const float* __restrict__ i0, __half* o0,
                             const float* __restrict__ i1, __half* o1,
                             const float* __restrict__ i2, __half* o2) {
    const long long n4 = (long long)B_*2048/4;
    const float* in; __half* out;
    if      (blockIdx.z == 0) { in = i0; out = o0; }
    else if (blockIdx.z == 1) { in = i1; out = o1; }
    else                      { in = i2; out = o2; }
    long long i  = blockIdx.x * (long long)blockDim.x + threadIdx.x;
    long long st = (long long)gridDim.x * blockDim.x;
    const float4* in4 = (const float4*)in;
    __half2* oo = (__half2*)out;
    for (; i < n4; i += st) {
        float4 v = in4[i];
        oo[2*i]   = __floats2half2_rn(v.x, v.y);
        oo[2*i+1] = __floats2half2_rn(v.z, v.w);
    }
}

__global__ void convW_kernel(const float* __restrict__ i0, __half* o0,
                             const float* __restrict__ i1, __half* o1,
                             const float* __restrict__ i2, __half* o2,
                             const float* __restrict__ i3, __half* o3,
                             const float* __restrict__ i4, __half* o4,
                             const float* __restrict__ i5, __half* o5) {
    const long long n4 = (long long)2048*2048/4;
    const float* in; __half* out;
    switch (blockIdx.z) {
        case 0: in = i0; out = o0; break;
        case 1: in = i1; out = o1; break;
        case 2: in = i2; out = o2; break;
        case 3: in = i3; out = o3; break;
        case 4: in = i4; out = o4; break;
        default: in = i5; out = o5; break;
    }
    long long i  = blockIdx.x * (long long)blockDim.x + threadIdx.x;
    long long st = (long long)gridDim.x * blockDim.x;
    const float4* in4 = (const float4*)in;
    __half2* oo = (__half2*)out;
    for (; i < n4; i += st) {
        float4 v = in4[i];
        oo[2*i]   = __floats2half2_rn(v.x, v.y);
        oo[2*i+1] = __floats2half2_rn(v.z, v.w);
    }
}

// ============ GEMM core: 128 threads, warp tile 64x64, 2 CTAs/SM ===========
struct FragCtx {
    uint32_t sbase;
    int srow; uint32_t sxor;
    uint32_t aRow, aKoff, bRow, bKoff, fxor;
    int wm, wn, qr, qc, warp, lane;
};

__device__ __forceinline__ void frag_init(FragCtx& f, uint32_t sbase) {
    const int tid = threadIdx.x;
    f.sbase = sbase;
    f.warp = tid >> 5; f.lane = tid & 31;
    f.wm = f.warp & 1; f.wn = f.warp >> 1;      // 2x2 warp grid
    f.qr = f.lane >> 2; f.qc = f.lane & 3;
    f.srow = tid;                                // 1 row per thread (128B)
    f.sxor = (uint32_t)((f.srow & 7) << 4);
    const int j = f.lane >> 3, rr = f.lane & 7;
    f.fxor = (uint32_t)(rr << 4);
    f.aRow  = (uint32_t)(f.wm*64 + (j&1)*8 + rr);
    f.aKoff = (uint32_t)((j>>1)*16);
    f.bRow  = (uint32_t)(f.wn*64 + (j>>1)*8 + rr);
    f.bKoff = (uint32_t)((j&1)*16);
}

// acc[4][8][4]: 4 m16 subtiles x 8 n8 subtiles
__device__ __forceinline__ void gemm_mainloop(
    const FragCtx& f, const __half* Ag, const __half* Bg, int K,
    float acc[4][8][4])
{
    #pragma unroll
    for (int i = 0; i < 4; i++)
        #pragma unroll
        for (int jn = 0; jn < 8; jn++)
            #pragma unroll
            for (int l = 0; l < 4; l++) acc[i][jn][l] = 0.f;

    const int KT = K / BK;
    // prologue: stage 0 (per thread: one 128B A row + one 128B B row)
    {
        const uint32_t sA = f.sbase, sB = f.sbase + A_STAGE;
        #pragma unroll
        for (int i = 0; i < 8; i++) {
            uint32_t c = ((uint32_t)(i*16)) ^ f.sxor;
            cpa16(sA + f.srow*128 + c, Ag + i*8);
            cpa16(sB + f.srow*128 + c, Bg + i*8);
        }
        asm volatile("cp.async.commit_group;\n" ::);
        asm volatile("cp.async.wait_group 0;\n" ::);
        __syncthreads();
    }
    int buf = 0;
    for (int kt = 0; kt < KT; kt++) {
        if (kt + 1 < KT) {
            const int nbuf = buf ^ 1;
            const uint32_t sA = f.sbase + nbuf*STAGE_B, sB = sA + A_STAGE;
            const __half* Agk = Ag + (kt+1)*BK;
            const __half* Bgk = Bg + (kt+1)*BK;
            #pragma unroll
            for (int i = 0; i < 8; i++) {
                uint32_t c = ((uint32_t)(i*16)) ^ f.sxor;
                cpa16(sA + f.srow*128 + c, Agk + i*8);
                cpa16(sB + f.srow*128 + c, Bgk + i*8);
            }
            asm volatile("cp.async.commit_group;\n" ::);
        }
        const uint32_t aBase = f.sbase + buf*STAGE_B + f.aRow*128;
        const uint32_t bBase = f.sbase + buf*STAGE_B + A_STAGE + f.bRow*128;
        #pragma unroll
        for (int ks = 0; ks < BK/16; ks++) {
            uint32_t afr[4][4];
            const uint32_t ac = ((uint32_t)(ks*32) + f.aKoff) ^ f.fxor;
            #pragma unroll
            for (int mt = 0; mt < 4; mt++)
                ldsm4(afr[mt], aBase + mt*16*128 + ac);
            uint32_t bfr[16];
            const uint32_t bc = ((uint32_t)(ks*32) + f.bKoff) ^ f.fxor;
            #pragma unroll
            for (int t = 0; t < 4; t++)
                ldsm4(bfr + t*4, bBase + t*16*128 + bc);
            #pragma unroll
            for (int mt = 0; mt < 4; mt++)
                #pragma unroll
                for (int nt = 0; nt < 8; nt++)
                    mma_f16(acc[mt][nt], afr[mt], bfr + nt*2);
        }
        asm volatile("cp.async.wait_group 0;\n" ::);
        __syncthreads();
        buf ^= 1;
    }
}

// ---------------- kv projection GEMM (fp16 out, W split) -------------------
__global__ __launch_bounds__(NTHREADS, 2)
void gemm_kv_kernel(const __half* __restrict__ A,
                    const __half* __restrict__ W0, const __half* __restrict__ W1,
                    const float* __restrict__ bias0, const float* __restrict__ bias1,
                    __half* __restrict__ C) {
    extern __shared__ __align__(1024) char smem[];
    FragCtx f; frag_init(f, (uint32_t)__cvta_generic_to_shared(smem));
    const int nb = blockIdx.x, mb = blockIdx.y;
    const int N = 2*FEAT_, K = FEAT_;
    const __half* Wp; const float* biasP; int nloc0;
    if (nb*BN < FEAT_) { Wp = W0; biasP = bias0; nloc0 = nb*BN; }
    else               { Wp = W1; biasP = bias1; nloc0 = nb*BN - FEAT_; }
    const __half* Ag = A  + (size_t)(mb*BM + f.srow)*K;
    const __half* Bg = Wp + (size_t)(nloc0 + f.srow)*K;

    float acc[4][8][4];
    gemm_mainloop(f, Ag, Bg, K, acc);

    float bv0[8], bv1[8];
    #pragma unroll
    for (int nt = 0; nt < 8; nt++) {
        int cl = nloc0 + f.wn*64 + nt*8 + f.qc*2;
        bv0[nt] = biasP[cl]; bv1[nt] = biasP[cl + 1];
    }
    #pragma unroll
    for (int mt = 0; mt < 4; mt++) {
        int r0 = mb*BM + f.wm*64 + mt*16 + f.qr;
        #pragma unroll
        for (int nt = 0; nt < 8; nt++) {
            int c0 = nb*BN + f.wn*64 + nt*8 + f.qc*2;
            size_t o0 = (size_t)r0*N + c0;
            size_t o1 = o0 + (size_t)8*N;
            *(__half2*)(C + o0) = __floats2half2_rn(acc[mt][nt][0]+bv0[nt], acc[mt][nt][1]+bv1[nt]);
            *(__half2*)(C + o1) = __floats2half2_rn(acc[mt][nt][2]+bv0[nt], acc[mt][nt][3]+bv1[nt]);
        }
    }
}

// ---------------- q projection GEMM (fp16 out, single W) -------------------
__global__ __launch_bounds__(NTHREADS, 2)
void gemm_q_kernel(const __half* __restrict__ A,
                   const __half* __restrict__ W,
                   const float* __restrict__ bias,
                   __half* __restrict__ C) {
    extern __shared__ __align__(1024) char smem[];
    FragCtx f; frag_init(f, (uint32_t)__cvta_generic_to_shared(smem));
    const int nb = blockIdx.x, mb = blockIdx.y;
    const int N = FEAT_, K = CURD;
    const int nloc0 = nb*BN;
    const __half* Ag = A + (size_t)(mb*BM + f.srow)*K;
    const __half* Bg = W + (size_t)(nloc0 + f.srow)*K;

    float acc[4][8][4];
    gemm_mainloop(f, Ag, Bg, K, acc);

    float bv0[8], bv1[8];
    #pragma unroll
    for (int nt = 0; nt < 8; nt++) {
        int cl = nloc0 + f.wn*64 + nt*8 + f.qc*2;
        bv0[nt] = bias[cl]; bv1[nt] = bias[cl + 1];
    }
    #pragma unroll
    for (int mt = 0; mt < 4; mt++) {
        int r0 = mb*BM + f.wm*64 + mt*16 + f.qr;
        #pragma unroll
        for (int nt = 0; nt < 8; nt++) {
            int c0 = nloc0 + f.wn*64 + nt*8 + f.qc*2;
            size_t o0 = (size_t)r0*N + c0;
            size_t o1 = o0 + (size_t)8*N;
            *(__half2*)(C + o0) = __floats2half2_rn(acc[mt][nt][0]+bv0[nt], acc[mt][nt][1]+bv1[nt]);
            *(__half2*)(C + o1) = __floats2half2_rn(acc[mt][nt][2]+bv0[nt], acc[mt][nt][3]+bv1[nt]);
        }
    }
}

// ---------------- Wo GEMM: y = x + attn @ Wo^T + bo (fp32 out) -------------
__global__ __launch_bounds__(NTHREADS, 2)
void gemm_wo_kernel(const __half* __restrict__ A,
                    const __half* __restrict__ W,
                    const float* __restrict__ bias,
                    const float* __restrict__ res,
                    float* __restrict__ C) {
    extern __shared__ __align__(1024) char smem[];
    FragCtx f; frag_init(f, (uint32_t)__cvta_generic_to_shared(smem));
    const int nb = blockIdx.x, mb = blockIdx.y;
    const int N = CURD, K = FEAT_;
    const int nloc0 = nb*BN;
    const __half* Ag = A + (size_t)(mb*BM + f.srow)*K;
    const __half* Bg = W + (size_t)(nloc0 + f.srow)*K;

    float acc[4][8][4];
    gemm_mainloop(f, Ag, Bg, K, acc);

    float bv0[8], bv1[8];
    #pragma unroll
    for (int nt = 0; nt < 8; nt++) {
        int cl = nloc0 + f.wn*64 + nt*8 + f.qc*2;
        bv0[nt] = bias[cl]; bv1[nt] = bias[cl + 1];
    }
    #pragma unroll
    for (int mt = 0; mt < 4; mt++) {
        int r0 = mb*BM + f.wm*64 + mt*16 + f.qr;
        #pragma unroll
        for (int nt = 0; nt < 8; nt++) {
            int c0 = nloc0 + f.wn*64 + nt*8 + f.qc*2;
            size_t o0 = (size_t)r0*N + c0;
            size_t o1 = o0 + (size_t)8*N;
            float v0 = acc[mt][nt][0] + bv0[nt] + res[o0];
            float v1 = acc[mt][nt][1] + bv1[nt] + res[o0+1];
            float v2 = acc[mt][nt][2] + bv0[nt] + res[o1];
            float v3 = acc[mt][nt][3] + bv1[nt] + res[o1+1];
            *(float2*)(C + o0) = make_float2(v0, v1);
            *(float2*)(C + o1) = make_float2(v2, v3);
        }
    }
}

// ---------------- attention: one warp per (b, h); 2-key softmax -----------
__global__ void attn_kernel(const __half* __restrict__ q,
                            const __half* __restrict__ kv2,
                            const __half* __restrict__ kv3,
                            __half* __restrict__ attn,
                            float* __restrict__ wout) {
    int gw   = (blockIdx.x * blockDim.x + threadIdx.x) >> 5;   // b*16 + h
    int lane = threadIdx.x & 31;
    int b = gw >> 4;
    int h = gw & 15;
    size_t qoff = (size_t)b*FEAT_     + h*HDIM + lane*4;
    size_t koff = (size_t)b*(2*FEAT_) + h*HDIM + lane*4;

    uint2 qr = *(const uint2*)(q   + qoff);
    uint2 k2r = *(const uint2*)(kv2 + koff);
    uint2 k3r = *(const uint2*)(kv3 + koff);
    uint2 v2r = *(const uint2*)(kv2 + koff + FEAT_);
    uint2 v3r = *(const uint2*)(kv3 + koff + FEAT_);

    float2 qa = __half22float2(*(__half2*)&qr.x);
    float2 qb = __half22float2(*(__half2*)&qr.y);
    float2 k2a = __half22float2(*(__half2*)&k2r.x);
    float2 k2b = __half22float2(*(__half2*)&k2r.y);
    float2 k3a = __half22float2(*(__half2*)&k3r.x);
    float2 k3b = __half22float2(*(__half2*)&k3r.y);
    float2 v2a = __half22float2(*(__half2*)&v2r.x);
    float2 v2b = __half22float2(*(__half2*)&v2r.y);
    float2 v3a = __half22float2(*(__half2*)&v3r.x);
    float2 v3b = __half22float2(*(__half2*)&v3r.y);

    float s2 = qa.x*k2a.x + qa.y*k2a.y + qb.x*k2b.x + qb.y*k2b.y;
    float s3 = qa.x*k3a.x + qa.y*k3a.y + qb.x*k3b.x + qb.y*k3b.y;
    #pragma unroll
    for (int o = 16; o; o >>= 1) {
        s2 += __shfl_xor_sync(0xffffffffu, s2, o);
        s3 += __shfl_xor_sync(0xffffffffu, s3, o);
    }
    const float scale = 0.08838834764831845f;   // 1/sqrt(128)
    s2 *= scale; s3 *= scale;
    float m  = fmaxf(s2, s3);
    float e2 = expf(s2 - m), e3 = expf(s3 - m);
    float inv = 1.f / (e2 + e3);
    float w2 = e2 * inv, w3 = e3 * inv;

    __half2 p0 = __floats2half2_rn(w2*v2a.x + w3*v3a.x, w2*v2a.y + w3*v3a.y);
    __half2 p1 = __floats2half2_rn(w2*v2b.x + w3*v3b.x, w2*v2b.y + w3*v3b.y);
    uint2 ov;
    ov.x = *(uint32_t*)&p0;
    ov.y = *(uint32_t*)&p1;
    *(uint2*)(attn + qoff) = ov;

    if (lane == 0) {
        wout[(size_t)gw*2]     = w2;
        wout[(size_t)gw*2 + 1] = w3;
    }
}

// ---------------- LayerNorm: one block per row ----------------------------
__global__ void ln_kernel(const float* __restrict__ y,
                          const float* __restrict__ lw,
                          const float* __restrict__ lb,
                          float* __restrict__ out) {
    __shared__ float shs[8], shq[8];
    int row = blockIdx.x, t = threadIdx.x;
    const float4* yr = (const float4*)(y + (size_t)row*CURD);
    float4 a = yr[t];
    float4 b = yr[256 + t];
    float s  = a.x+a.y+a.z+a.w + b.x+b.y+b.z+b.w;
    float qq = a.x*a.x+a.y*a.y+a.z*a.z+a.w*a.w
             + b.x*b.x+b.y*b.y+b.z*b.z+b.w*b.w;
    #pragma unroll
    for (int o = 16; o; o >>= 1) {
        s  += __shfl_xor_sync(0xffffffffu, s,  o);
        qq += __shfl_xor_sync(0xffffffffu, qq, o);
    }
    int warp = t >> 5;
    if ((t & 31) == 0) { shs[warp] = s; shq[warp] = qq; }
    __syncthreads();
    float S = 0.f, Q = 0.f;
    #pragma unroll
    for (int i = 0; i < 8; i++) { S += shs[i]; Q += shq[i]; }
    float mean = S * (1.f/2048.f);
    float inv  = rsqrtf(Q * (1.f/2048.f) - mean*mean + 1e-5f);

    const float4* lw4 = (const float4*)lw;
    const float4* lb4 = (const float4*)lb;
    float4* orow = (float4*)(out + (size_t)row*CURD);
    float4 w, z, o4;
    w = lw4[t];       z = lb4[t];
    o4.x = w.x*(a.x-mean)*inv + z.x;
    o4.y = w.y*(a.y-mean)*inv + z.y;
    o4.z = w.z*(a.z-mean)*inv + z.z;
    o4.w = w.w*(a.w-mean)*inv + z.w;
    orow[t] = o4;
    w = lw4[256+t];   z = lb4[256+t];
    o4.x = w.x*(b.x-mean)*inv + z.x;
    o4.y = w.y*(b.y-mean)*inv + z.y;
    o4.z = w.z*(b.z-mean)*inv + z.z;
    o4.w = w.w*(b.w-mean)*inv + z.w;
    orow[256+t] = o4;
}

// ---------------- launch ---------------------------------------------------
extern "C" void kernel_launch(void* const* d_in, const int* in_sizes, int n_in,
                              void* d_out, int out_size) {
    const float* x   = (const float*)d_in[0];
    const float* v2  = (const float*)d_in[1];
    const float* v3  = (const float*)d_in[2];
    const float* Wq  = (const float*)d_in[3];
    const float* bq  = (const float*)d_in[4];
    const float* Wk2 = (const float*)d_in[5];
    const float* bk2 = (const float*)d_in[6];
    const float* Wk3 = (const float*)d_in[7];
    const float* bk3 = (const float*)d_in[8];
    const float* Wv2 = (const float*)d_in[9];
    const float* bv2 = (const float*)d_in[10];
    const float* Wv3 = (const float*)d_in[11];
    const float* bv3 = (const float*)d_in[12];
    const float* Wo  = (const float*)d_in[13];
    const float* bo  = (const float*)d_in[14];
    const float* lw  = (const float*)d_in[15];
    const float* lb  = (const float*)d_in[16];
    float* out = (float*)d_out;

    __half *xh, *v2h, *v3h, *wqh, *wk2h, *wv2h, *wk3h, *wv3h, *woh;
    __half *qb, *kv2, *kv3, *attn;
    float *yb;
    cudaGetSymbolAddress((void**)&xh,   g_xh);
    cudaGetSymbolAddress((void**)&v2h,  g_v2h);
    cudaGetSymbolAddress((void**)&v3h,  g_v3h);
    cudaGetSymbolAddress((void**)&wqh,  g_wqh);
    cudaGetSymbolAddress((void**)&wk2h, g_wk2h);
    cudaGetSymbolAddress((void**)&wv2h, g_wv2h);
    cudaGetSymbolAddress((void**)&wk3h, g_wk3h);
    cudaGetSymbolAddress((void**)&wv3h, g_wv3h);
    cudaGetSymbolAddress((void**)&woh,  g_woh);
    cudaGetSymbolAddress((void**)&qb,   g_q);
    cudaGetSymbolAddress((void**)&kv2,  g_kv2);
    cudaGetSymbolAddress((void**)&kv3,  g_kv3);
    cudaGetSymbolAddress((void**)&attn, g_att);
    cudaGetSymbolAddress((void**)&yb,   g_y);

    cudaFuncSetAttribute((const void*)gemm_kv_kernel,
                         cudaFuncAttributeMaxDynamicSharedMemorySize, SMEM_BYTES);
    cudaFuncSetAttribute((const void*)gemm_q_kernel,
                         cudaFuncAttributeMaxDynamicSharedMemorySize, SMEM_BYTES);
    cudaFuncSetAttribute((const void*)gemm_wo_kernel,
                         cudaFuncAttributeMaxDynamicSharedMemorySize, SMEM_BYTES);

    // conversions (2 merged launches)
    convA_kernel<<<dim3(2048, 1, 3), 256>>>(x, xh, v2, v2h, v3, v3h);
    convW_kernel<<<dim3(1024, 1, 6), 256>>>(Wq, wqh, Wk2, wk2h, Wv2, wv2h,
                                            Wk3, wk3h, Wv3, wv3h, Wo, woh);

    dim3 blk(NTHREADS);
    // q = x @ Wq^T + bq
    gemm_q_kernel<<<dim3(FEAT_/BN, B_/BM), blk, SMEM_BYTES>>>(xh, wqh, bq, qb);
    // [k2 | v2] and [k3 | v3]
    gemm_kv_kernel<<<dim3(2*FEAT_/BN, B_/BM), blk, SMEM_BYTES>>>(
        v2h, wk2h, wv2h, bk2, bv2, kv2);
    gemm_kv_kernel<<<dim3(2*FEAT_/BN, B_/BM), blk, SMEM_BYTES>>>(
        v3h, wk3h, wv3h, bk3, bv3, kv3);

    // attention + attn_weights (written to the tail of d_out)
    size_t woff = (size_t)out_size - (size_t)B_*HEADS_*2;
    attn_kernel<<<B_*HEADS_/8, 256>>>(qb, kv2, kv3, attn, out + woff);

    // y = x + attn @ Wo^T + bo
    gemm_wo_kernel<<<dim3(CURD/BN, B_/BM), blk, SMEM_BYTES>>>(
        attn, woh, bo, x, yb);

    // LayerNorm -> d_out
    ln_kernel<<<B_, 256>>>(yb, lw, lb, out);
}

// round 15
// speedup vs baseline: 1.4967x; 1.4967x over previous
#include <cuda_runtime.h>
#include <cuda_fp16.h>
#include <cstdint>

#define B_    16384
#define CURD  2048
#define FEAT_ 2048
#define HEADS_ 16
#define HDIM  128

#define NTHREADS 256
#define BM 128
#define BN 128
#define BK 64
// per stage: A 128 rows x 128B = 16 KB, B 128 rows x 128B = 16 KB
#define A_STAGE   16384
#define STAGE_B   (2*A_STAGE)          // 32 KB
#define SMEM_BYTES (2*STAGE_B)         // 2 stages = 64 KB -> 2 CTAs/SM

// ---------------- scratch (device globals; no allocation allowed) ----------
__device__ __align__(16) __half g_xh [(size_t)B_*CURD];
__device__ __align__(16) __half g_v2h[(size_t)B_*FEAT_];
__device__ __align__(16) __half g_v3h[(size_t)B_*FEAT_];
__device__ __align__(16) __half g_wqh [(size_t)FEAT_*CURD];
__device__ __align__(16) __half g_wk2h[(size_t)FEAT_*FEAT_];
__device__ __align__(16) __half g_wv2h[(size_t)FEAT_*FEAT_];
__device__ __align__(16) __half g_wk3h[(size_t)FEAT_*FEAT_];
__device__ __align__(16) __half g_wv3h[(size_t)FEAT_*FEAT_];
__device__ __align__(16) __half g_woh [(size_t)CURD*FEAT_];
__device__ __align__(16) __half g_q  [(size_t)B_*FEAT_];
__device__ __align__(16) __half g_kv2[(size_t)B_*2*FEAT_];
__device__ __align__(16) __half g_kv3[(size_t)B_*2*FEAT_];
__device__ __align__(16) __half g_att[(size_t)B_*FEAT_];
__device__ __align__(16) float  g_y  [(size_t)B_*CURD];

// ---------------- helpers ----------------
__device__ __forceinline__ void cpa16(uint32_t s, const void* g) {
    asm volatile("cp.async.cg.shared.global [%0], [%1], 16;\n" :: "r"(s), "l"(g));
}

__device__ __forceinline__ void ldsm4(uint32_t* r, uint32_t addr) {
    asm volatile("ldmatrix.sync.aligned.m8n8.x4.shared.b16 {%0,%1,%2,%3}, [%4];"
        : "=r"(r[0]), "=r"(r[1]), "=r"(r[2]), "=r"(r[3]) : "r"(addr));
}

__device__ __forceinline__ void mma_f16(float* c, const uint32_t* a, const uint32_t* b) {
    asm volatile(
        "mma.sync.aligned.m16n8k16.row.col.f32.f16.f16.f32 "
        "{%0,%1,%2,%3}, {%4,%5,%6,%7}, {%8,%9}, {%0,%1,%2,%3};"
        : "+f"(c[0]), "+f"(c[1]), "+f"(c[2]), "+f"(c[3])
        : "r"(a[0]), "r"(a[1]), "r"(a[2]), "r"(a[3]),
          "r"(b[0]), "r"(b[1]));
}

// ---------------- fp32 -> fp16 conversion (RN) ------------------------------
__global__ void conv_h_kernel(const float* __restrict__ in,
                              __half* __restrict__ out, long long n4) {
    long long i  = blockIdx.x * (long long)blockDim.x + threadIdx.x;
    long long st = (long long)gridDim.x * blockDim.x;
    const float4* in4 = (const float4*)in;
    __half2* o2 = (__half2*)out;
    for (; i < n4; i += st) {
        float4 v = in4[i];
        o2[2*i]   = __floats2half2_rn(v.x, v.y);
        o2[2*i+1] = __floats2half2_rn(v.z, v.w);
    }
}

// ---------------- FP16 GEMM (R8-validated):  C = A @ W^T + bias (+res)
// CTA tile 128x128, warp grid 2(M) x 4(N), warp tile 64x32, 2 CTAs/SM.
// SW128-swizzled smem, ldmatrix loads, 2-stage cp.async double buffer.
// W split into two stacked halves (W0 rows [0,Nsplit), W1 the rest).
template<bool RES, bool HOUT>
__global__ __launch_bounds__(NTHREADS, 2)
void gemm_f16_kernel(const __half* __restrict__ A,
                     const __half* __restrict__ W0,
                     const __half* __restrict__ W1,
                     int Nsplit,
                     const float* __restrict__ bias0,
                     const float* __restrict__ bias1,
                     const float* __restrict__ res,
                     void* __restrict__ Cv,
                     int N, int K) {
    extern __shared__ __align__(1024) char smem[];
    const uint32_t sbase = (uint32_t)__cvta_generic_to_shared(smem);

    const int nb = blockIdx.x, mb = blockIdx.y;
    const __half* Wp; const float* biasP; int nloc0;
    if (nb*BN < Nsplit) { Wp = W0; biasP = bias0; nloc0 = nb*BN; }
    else                { Wp = W1; biasP = bias1; nloc0 = nb*BN - Nsplit; }

    const int tid  = threadIdx.x;
    const int warp = tid >> 5, lane = tid & 31;
    const int wm = warp & 1;           // 2 M-rows of warps (64 rows each)
    const int wn = warp >> 1;          // 4 N-cols of warps (32 cols each)
    const int qr = lane >> 2, qc = lane & 3;

    // staging: per thread one half-row (64B = 4x16B)
    const int srow = tid >> 1;
    const int scol = (tid & 1) * 64;
    const uint32_t sxor = (uint32_t)((srow & 7) << 4);
    const __half* Ag = A  + (size_t)(mb*BM + srow)*K + scol/2;
    const __half* Bg = Wp + (size_t)(nloc0 + srow)*K + scol/2;

    // ldmatrix addressing
    const int j  = lane >> 3;
    const int rr = lane & 7;
    const uint32_t fxor = (uint32_t)(rr << 4);
    const uint32_t aRow  = (uint32_t)(wm*64 + (j&1)*8 + rr);
    const uint32_t aKoff = (uint32_t)((j>>1)*16);
    const uint32_t bRow  = (uint32_t)(wn*32 + (j>>1)*8 + rr);
    const uint32_t bKoff = (uint32_t)((j&1)*16);

    float acc[4][4][4];
    #pragma unroll
    for (int i = 0; i < 4; i++)
        #pragma unroll
        for (int jn = 0; jn < 4; jn++)
            #pragma unroll
            for (int l = 0; l < 4; l++) acc[i][jn][l] = 0.f;

    const int KT = K / BK;

    // prologue: stage 0
    {
        const uint32_t sA = sbase, sB = sbase + A_STAGE;
        #pragma unroll
        for (int i = 0; i < 4; i++) {
            uint32_t c = ((uint32_t)(scol + i*16)) ^ sxor;
            cpa16(sA + srow*128 + c, Ag + i*8);
            cpa16(sB + srow*128 + c, Bg + i*8);
        }
        asm volatile("cp.async.commit_group;\n" ::);
        asm volatile("cp.async.wait_group 0;\n" ::);
        __syncthreads();
    }

    int buf = 0;
    for (int kt = 0; kt < KT; kt++) {
        if (kt + 1 < KT) {
            const int nbuf = buf ^ 1;
            const uint32_t sA = sbase + nbuf*STAGE_B, sB = sA + A_STAGE;
            const __half* Agk = Ag + (kt+1)*BK;
            const __half* Bgk = Bg + (kt+1)*BK;
            #pragma unroll
            for (int i = 0; i < 4; i++) {
                uint32_t c = ((uint32_t)(scol + i*16)) ^ sxor;
                cpa16(sA + srow*128 + c, Agk + i*8);
                cpa16(sB + srow*128 + c, Bgk + i*8);
            }
            asm volatile("cp.async.commit_group;\n" ::);
        }

        const uint32_t aBase = sbase + buf*STAGE_B + aRow*128;
        const uint32_t bBase = sbase + buf*STAGE_B + A_STAGE + bRow*128;
        #pragma unroll
        for (int ks = 0; ks < BK/16; ks++) {
            uint32_t afr[4][4];
            const uint32_t ac = ((uint32_t)(ks*32) + aKoff) ^ fxor;
            #pragma unroll
            for (int mt = 0; mt < 4; mt++)
                ldsm4(afr[mt], aBase + mt*16*128 + ac);
            uint32_t bfr[8];
            const uint32_t bc = ((uint32_t)(ks*32) + bKoff) ^ fxor;
            ldsm4(bfr,     bBase + bc);
            ldsm4(bfr + 4, bBase + 16*128 + bc);
            #pragma unroll
            for (int mt = 0; mt < 4; mt++)
                #pragma unroll
                for (int nt = 0; nt < 4; nt++)
                    mma_f16(acc[mt][nt], afr[mt], bfr + nt*2);
        }

        asm volatile("cp.async.wait_group 0;\n" ::);
        __syncthreads();
        buf ^= 1;
    }

    // epilogue: bias (+residual), fp16 or fp32 stores
    float bv0[4], bv1[4];
    #pragma unroll
    for (int nt = 0; nt < 4; nt++) {
        int cl = nloc0 + wn*32 + nt*8 + qc*2;
        bv0[nt] = biasP[cl];
        bv1[nt] = biasP[cl + 1];
    }
    #pragma unroll
    for (int mt = 0; mt < 4; mt++) {
        int r0 = mb*BM + wm*64 + mt*16 + qr;
        #pragma unroll
        for (int nt = 0; nt < 4; nt++) {
            int c0 = nb*BN + wn*32 + nt*8 + qc*2;
            size_t o0 = (size_t)r0*N + c0;
            size_t o1 = o0 + (size_t)8*N;
            float v0 = acc[mt][nt][0] + bv0[nt];
            float v1 = acc[mt][nt][1] + bv1[nt];
            float v2 = acc[mt][nt][2] + bv0[nt];
            float v3 = acc[mt][nt][3] + bv1[nt];
            if (HOUT) {
                __half* C = (__half*)Cv;
                *(__half2*)(C + o0) = __floats2half2_rn(v0, v1);
                *(__half2*)(C + o1) = __floats2half2_rn(v2, v3);
            } else {
                float* C = (float*)Cv;
                if (RES) {
                    v0 += res[o0]; v1 += res[o0 + 1];
                    v2 += res[o1]; v3 += res[o1 + 1];
                }
                *(float2*)(C + o0) = make_float2(v0, v1);
                *(float2*)(C + o1) = make_float2(v2, v3);
            }
        }
    }
}

// ---------------- attention: one warp per (b, h); 2-key softmax -----------
__global__ void attn_kernel(const __half* __restrict__ q,
                            const __half* __restrict__ kv2,
                            const __half* __restrict__ kv3,
                            __half* __restrict__ attn,
                            float* __restrict__ wout) {
    int gw   = (blockIdx.x * blockDim.x + threadIdx.x) >> 5;   // b*16 + h
    int lane = threadIdx.x & 31;
    int b = gw >> 4;
    int h = gw & 15;
    size_t qoff = (size_t)b*FEAT_     + h*HDIM + lane*4;
    size_t koff = (size_t)b*(2*FEAT_) + h*HDIM + lane*4;

    uint2 qr = *(const uint2*)(q   + qoff);
    uint2 k2r = *(const uint2*)(kv2 + koff);
    uint2 k3r = *(const uint2*)(kv3 + koff);
    uint2 v2r = *(const uint2*)(kv2 + koff + FEAT_);
    uint2 v3r = *(const uint2*)(kv3 + koff + FEAT_);

    float2 qa = __half22float2(*(__half2*)&qr.x);
    float2 qb = __half22float2(*(__half2*)&qr.y);
    float2 k2a = __half22float2(*(__half2*)&k2r.x);
    float2 k2b = __half22float2(*(__half2*)&k2r.y);
    float2 k3a = __half22float2(*(__half2*)&k3r.x);
    float2 k3b = __half22float2(*(__half2*)&k3r.y);
    float2 v2a = __half22float2(*(__half2*)&v2r.x);
    float2 v2b = __half22float2(*(__half2*)&v2r.y);
    float2 v3a = __half22float2(*(__half2*)&v3r.x);
    float2 v3b = __half22float2(*(__half2*)&v3r.y);

    float s2 = qa.x*k2a.x + qa.y*k2a.y + qb.x*k2b.x + qb.y*k2b.y;
    float s3 = qa.x*k3a.x + qa.y*k3a.y + qb.x*k3b.x + qb.y*k3b.y;
    #pragma unroll
    for (int o = 16; o; o >>= 1) {
        s2 += __shfl_xor_sync(0xffffffffu, s2, o);
        s3 += __shfl_xor_sync(0xffffffffu, s3, o);
    }
    const float scale = 0.08838834764831845f;   // 1/sqrt(128)
    s2 *= scale; s3 *= scale;
    float m  = fmaxf(s2, s3);
    float e2 = expf(s2 - m), e3 = expf(s3 - m);
    float inv = 1.f / (e2 + e3);
    float w2 = e2 * inv, w3 = e3 * inv;

    __half2 p0 = __floats2half2_rn(w2*v2a.x + w3*v3a.x, w2*v2a.y + w3*v3a.y);
    __half2 p1 = __floats2half2_rn(w2*v2b.x + w3*v3b.x, w2*v2b.y + w3*v3b.y);
    uint2 ov;
    ov.x = *(uint32_t*)&p0;
    ov.y = *(uint32_t*)&p1;
    *(uint2*)(attn + qoff) = ov;

    if (lane == 0) {
        wout[(size_t)gw*2]     = w2;
        wout[(size_t)gw*2 + 1] = w3;
    }
}

// ---------------- LayerNorm: one block per row ----------------------------
__global__ void ln_kernel(const float* __restrict__ y,
                          const float* __restrict__ lw,
                          const float* __restrict__ lb,
                          float* __restrict__ out) {
    __shared__ float shs[8], shq[8];
    int row = blockIdx.x, t = threadIdx.x;
    const float4* yr = (const float4*)(y + (size_t)row*CURD);
    float4 a = yr[t];
    float4 b = yr[256 + t];
    float s  = a.x+a.y+a.z+a.w + b.x+b.y+b.z+b.w;
    float qq = a.x*a.x+a.y*a.y+a.z*a.z+a.w*a.w
             + b.x*b.x+b.y*b.y+b.z*b.z+b.w*b.w;
    #pragma unroll
    for (int o = 16; o; o >>= 1) {
        s  += __shfl_xor_sync(0xffffffffu, s,  o);
        qq += __shfl_xor_sync(0xffffffffu, qq, o);
    }
    int warp = t >> 5;
    if ((t & 31) == 0) { shs[warp] = s; shq[warp] = qq; }
    __syncthreads();
    float S = 0.f, Q = 0.f;
    #pragma unroll
    for (int i = 0; i < 8; i++) { S += shs[i]; Q += shq[i]; }
    float mean = S * (1.f/2048.f);
    float inv  = rsqrtf(Q * (1.f/2048.f) - mean*mean + 1e-5f);

    const float4* lw4 = (const float4*)lw;
    const float4* lb4 = (const float4*)lb;
    float4* orow = (float4*)(out + (size_t)row*CURD);
    float4 w, z, o4;
    w = lw4[t];       z = lb4[t];
    o4.x = w.x*(a.x-mean)*inv + z.x;
    o4.y = w.y*(a.y-mean)*inv + z.y;
    o4.z = w.z*(a.z-mean)*inv + z.z;
    o4.w = w.w*(a.w-mean)*inv + z.w;
    orow[t] = o4;
    w = lw4[256+t];   z = lb4[256+t];
    o4.x = w.x*(b.x-mean)*inv + z.x;
    o4.y = w.y*(b.y-mean)*inv + z.y;
    o4.z = w.z*(b.z-mean)*inv + z.z;
    o4.w = w.w*(b.w-mean)*inv + z.w;
    orow[256+t] = o4;
}

// ---------------- launch: fork/join streams inside graph capture -----------
extern "C" void kernel_launch(void* const* d_in, const int* in_sizes, int n_in,
                              void* d_out, int out_size) {
    const float* x   = (const float*)d_in[0];
    const float* v2  = (const float*)d_in[1];
    const float* v3  = (const float*)d_in[2];
    const float* Wq  = (const float*)d_in[3];
    const float* bq  = (const float*)d_in[4];
    const float* Wk2 = (const float*)d_in[5];
    const float* bk2 = (const float*)d_in[6];
    const float* Wk3 = (const float*)d_in[7];
    const float* bk3 = (const float*)d_in[8];
    const float* Wv2 = (const float*)d_in[9];
    const float* bv2 = (const float*)d_in[10];
    const float* Wv3 = (const float*)d_in[11];
    const float* bv3 = (const float*)d_in[12];
    const float* Wo  = (const float*)d_in[13];
    const float* bo  = (const float*)d_in[14];
    const float* lw  = (const float*)d_in[15];
    const float* lb  = (const float*)d_in[16];
    float* out = (float*)d_out;

    __half *xh, *v2h, *v3h, *wqh, *wk2h, *wv2h, *wk3h, *wv3h, *woh;
    __half *qb, *kv2, *kv3, *attn;
    float *yb;
    cudaGetSymbolAddress((void**)&xh,   g_xh);
    cudaGetSymbolAddress((void**)&v2h,  g_v2h);
    cudaGetSymbolAddress((void**)&v3h,  g_v3h);
    cudaGetSymbolAddress((void**)&wqh,  g_wqh);
    cudaGetSymbolAddress((void**)&wk2h, g_wk2h);
    cudaGetSymbolAddress((void**)&wv2h, g_wv2h);
    cudaGetSymbolAddress((void**)&wk3h, g_wk3h);
    cudaGetSymbolAddress((void**)&wv3h, g_wv3h);
    cudaGetSymbolAddress((void**)&woh,  g_woh);
    cudaGetSymbolAddress((void**)&qb,   g_q);
    cudaGetSymbolAddress((void**)&kv2,  g_kv2);
    cudaGetSymbolAddress((void**)&kv3,  g_kv3);
    cudaGetSymbolAddress((void**)&attn, g_att);
    cudaGetSymbolAddress((void**)&yb,   g_y);

    cudaFuncSetAttribute((const void*)gemm_f16_kernel<false,true>,
                         cudaFuncAttributeMaxDynamicSharedMemorySize, SMEM_BYTES);
    cudaFuncSetAttribute((const void*)gemm_f16_kernel<true,false>,
                         cudaFuncAttributeMaxDynamicSharedMemorySize, SMEM_BYTES);

    // side streams + fork/join events (capture-safe pattern)
    cudaStream_t s1, s2, s3;
    cudaStreamCreateWithFlags(&s1, cudaStreamNonBlocking);
    cudaStreamCreateWithFlags(&s2, cudaStreamNonBlocking);
    cudaStreamCreateWithFlags(&s3, cudaStreamNonBlocking);
    cudaEvent_t e0, e1, e2, e3;
    cudaEventCreateWithFlags(&e0, cudaEventDisableTiming);
    cudaEventCreateWithFlags(&e1, cudaEventDisableTiming);
    cudaEventCreateWithFlags(&e2, cudaEventDisableTiming);
    cudaEventCreateWithFlags(&e3, cudaEventDisableTiming);

    const int RG = 2048, RT = 256;
    dim3 blk(NTHREADS);

    // fork from the (captured) default stream
    cudaEventRecord(e0, 0);
    cudaStreamWaitEvent(s1, e0, 0);
    cudaStreamWaitEvent(s2, e0, 0);
    cudaStreamWaitEvent(s3, e0, 0);

    // --- stream s1: kv2 chain ---
    conv_h_kernel<<<RG, RT, 0, s1>>>(v2,  v2h, (long long)B_*FEAT_/4);
    conv_h_kernel<<<RG, RT, 0, s1>>>(Wk2, wk2h,(long long)FEAT_*FEAT_/4);
    conv_h_kernel<<<RG, RT, 0, s1>>>(Wv2, wv2h,(long long)FEAT_*FEAT_/4);
    gemm_f16_kernel<false,true><<<dim3(2*FEAT_/BN, B_/BM), blk, SMEM_BYTES, s1>>>(
        v2h, wk2h, wv2h, FEAT_, bk2, bv2, nullptr, kv2, 2*FEAT_, FEAT_);
    cudaEventRecord(e1, s1);

    // --- stream s2: kv3 chain ---
    conv_h_kernel<<<RG, RT, 0, s2>>>(v3,  v3h, (long long)B_*FEAT_/4);
    conv_h_kernel<<<RG, RT, 0, s2>>>(Wk3, wk3h,(long long)FEAT_*FEAT_/4);
    conv_h_kernel<<<RG, RT, 0, s2>>>(Wv3, wv3h,(long long)FEAT_*FEAT_/4);
    gemm_f16_kernel<false,true><<<dim3(2*FEAT_/BN, B_/BM), blk, SMEM_BYTES, s2>>>(
        v3h, wk3h, wv3h, FEAT_, bk3, bv3, nullptr, kv3, 2*FEAT_, FEAT_);
    cudaEventRecord(e2, s2);

    // --- stream s3: Wo conversion (needed only by the final GEMM) ---
    conv_h_kernel<<<RG, RT, 0, s3>>>(Wo, woh, (long long)CURD*FEAT_/4);
    cudaEventRecord(e3, s3);

    // --- main stream: q chain ---
    conv_h_kernel<<<RG, RT>>>(x,  xh,  (long long)B_*CURD/4);
    conv_h_kernel<<<RG, RT>>>(Wq, wqh, (long long)FEAT_*CURD/4);
    gemm_f16_kernel<false,true><<<dim3(FEAT_/BN, B_/BM), blk, SMEM_BYTES>>>(
        xh, wqh, wqh, FEAT_, bq, bq, nullptr, qb, FEAT_, CURD);

    // join kv chains, then attention (+ attn_weights to tail of d_out)
    cudaStreamWaitEvent(0, e1, 0);
    cudaStreamWaitEvent(0, e2, 0);
    size_t woff = (size_t)out_size - (size_t)B_*HEADS_*2;
    attn_kernel<<<B_*HEADS_/8, 256>>>(qb, kv2, kv3, attn, out + woff);

    // join Wo conversion, then y = x + attn @ Wo^T + bo
    cudaStreamWaitEvent(0, e3, 0);
    gemm_f16_kernel<true,false><<<dim3(CURD/BN, B_/BM), blk, SMEM_BYTES>>>(
        attn, woh, woh, CURD, bo, bo, x, yb, CURD, FEAT_);

    // LayerNorm -> d_out
    ln_kernel<<<B_, 256>>>(yb, lw, lb, out);

    // destroy resources only when NOT capturing (destroying a capturing
    // stream would invalidate the graph); the capture call leaks 3 streams
    // + 4 events once, which allocates no tracked device memory.
    cudaStreamCaptureStatus cs = cudaStreamCaptureStatusNone;
    cudaStreamIsCapturing(0, &cs);
    if (cs == cudaStreamCaptureStatusNone) {
        cudaEventDestroy(e0); cudaEventDestroy(e1);
        cudaEventDestroy(e2); cudaEventDestroy(e3);
        cudaStreamDestroy(s1); cudaStreamDestroy(s2); cudaStreamDestroy(s3);
    }
}

// round 16
// speedup vs baseline: 1.5046x; 1.0053x over previous
#include <cuda_runtime.h>
#include <cuda_fp16.h>
#include <cstdint>

#define B_    16384
#define HALF_ (B_/2)
#define CURD  2048
#define FEAT_ 2048
#define HEADS_ 16
#define HDIM  128

#define NTHREADS 256
#define BM 128
#define BN 128
#define BK 64
#define A_STAGE   16384
#define STAGE_B   (2*A_STAGE)          // 32 KB
#define SMEM_BYTES (2*STAGE_B)         // 2 stages = 64 KB -> 2 CTAs/SM

// ---------------- scratch (device globals; no allocation allowed) ----------
__device__ __align__(16) __half g_xh [(size_t)B_*CURD];
__device__ __align__(16) __half g_v2h[(size_t)B_*FEAT_];
__device__ __align__(16) __half g_v3h[(size_t)B_*FEAT_];
__device__ __align__(16) __half g_wqh [(size_t)FEAT_*CURD];
__device__ __align__(16) __half g_wk2h[(size_t)FEAT_*FEAT_];
__device__ __align__(16) __half g_wv2h[(size_t)FEAT_*FEAT_];
__device__ __align__(16) __half g_wk3h[(size_t)FEAT_*FEAT_];
__device__ __align__(16) __half g_wv3h[(size_t)FEAT_*FEAT_];
__device__ __align__(16) __half g_woh [(size_t)CURD*FEAT_];
__device__ __align__(16) __half g_q  [(size_t)B_*FEAT_];
__device__ __align__(16) __half g_kv2[(size_t)B_*2*FEAT_];
__device__ __align__(16) __half g_kv3[(size_t)B_*2*FEAT_];
__device__ __align__(16) __half g_att[(size_t)B_*FEAT_];
__device__ __align__(16) float  g_y  [(size_t)B_*CURD];

// ---------------- helpers ----------------
__device__ __forceinline__ void cpa16(uint32_t s, const void* g) {
    asm volatile("cp.async.cg.shared.global [%0], [%1], 16;\n" :: "r"(s), "l"(g));
}

__device__ __forceinline__ void ldsm4(uint32_t* r, uint32_t addr) {
    asm volatile("ldmatrix.sync.aligned.m8n8.x4.shared.b16 {%0,%1,%2,%3}, [%4];"
        : "=r"(r[0]), "=r"(r[1]), "=r"(r[2]), "=r"(r[3]) : "r"(addr));
}

__device__ __forceinline__ void mma_f16(float* c, const uint32_t* a, const uint32_t* b) {
    asm volatile(
        "mma.sync.aligned.m16n8k16.row.col.f32.f16.f16.f32 "
        "{%0,%1,%2,%3}, {%4,%5,%6,%7}, {%8,%9}, {%0,%1,%2,%3};"
        : "+f"(c[0]), "+f"(c[1]), "+f"(c[2]), "+f"(c[3])
        : "r"(a[0]), "r"(a[1]), "r"(a[2]), "r"(a[3]),
          "r"(b[0]), "r"(b[1]));
}

// ---------------- fp32 -> fp16 conversion (RN) ------------------------------
__global__ void conv_h_kernel(const float* __restrict__ in,
                              __half* __restrict__ out, long long n4) {
    long long i  = blockIdx.x * (long long)blockDim.x + threadIdx.x;
    long long st = (long long)gridDim.x * blockDim.x;
    const float4* in4 = (const float4*)in;
    __half2* o2 = (__half2*)out;
    for (; i < n4; i += st) {
        float4 v = in4[i];
        o2[2*i]   = __floats2half2_rn(v.x, v.y);
        o2[2*i+1] = __floats2half2_rn(v.z, v.w);
    }
}

// ---------------- FP16 GEMM (R8-validated core):  C = A @ W^T + bias (+res)
// CTA tile 128x128, warp grid 2(M) x 4(N), warp tile 64x32, 2 CTAs/SM.
// Pointers may be pre-offset by a row block; grid.y spans only that block.
template<bool RES, bool HOUT>
__global__ __launch_bounds__(NTHREADS, 2)
void gemm_f16_kernel(const __half* __restrict__ A,
                     const __half* __restrict__ W0,
                     const __half* __restrict__ W1,
                     int Nsplit,
                     const float* __restrict__ bias0,
                     const float* __restrict__ bias1,
                     const float* __restrict__ res,
                     void* __restrict__ Cv,
                     int N, int K) {
    extern __shared__ __align__(1024) char smem[];
    const uint32_t sbase = (uint32_t)__cvta_generic_to_shared(smem);

    const int nb = blockIdx.x, mb = blockIdx.y;
    const __half* Wp; const float* biasP; int nloc0;
    if (nb*BN < Nsplit) { Wp = W0; biasP = bias0; nloc0 = nb*BN; }
    else                { Wp = W1; biasP = bias1; nloc0 = nb*BN - Nsplit; }

    const int tid  = threadIdx.x;
    const int warp = tid >> 5, lane = tid & 31;
    const int wm = warp & 1;
    const int wn = warp >> 1;
    const int qr = lane >> 2, qc = lane & 3;

    const int srow = tid >> 1;
    const int scol = (tid & 1) * 64;
    const uint32_t sxor = (uint32_t)((srow & 7) << 4);
    const __half* Ag = A  + (size_t)(mb*BM + srow)*K + scol/2;
    const __half* Bg = Wp + (size_t)(nloc0 + srow)*K + scol/2;

    const int j  = lane >> 3;
    const int rr = lane & 7;
    const uint32_t fxor = (uint32_t)(rr << 4);
    const uint32_t aRow  = (uint32_t)(wm*64 + (j&1)*8 + rr);
    const uint32_t aKoff = (uint32_t)((j>>1)*16);
    const uint32_t bRow  = (uint32_t)(wn*32 + (j>>1)*8 + rr);
    const uint32_t bKoff = (uint32_t)((j&1)*16);

    float acc[4][4][4];
    #pragma unroll
    for (int i = 0; i < 4; i++)
        #pragma unroll
        for (int jn = 0; jn < 4; jn++)
            #pragma unroll
            for (int l = 0; l < 4; l++) acc[i][jn][l] = 0.f;

    const int KT = K / BK;

    {
        const uint32_t sA = sbase, sB = sbase + A_STAGE;
        #pragma unroll
        for (int i = 0; i < 4; i++) {
            uint32_t c = ((uint32_t)(scol + i*16)) ^ sxor;
            cpa16(sA + srow*128 + c, Ag + i*8);
            cpa16(sB + srow*128 + c, Bg + i*8);
        }
        asm volatile("cp.async.commit_group;\n" ::);
        asm volatile("cp.async.wait_group 0;\n" ::);
        __syncthreads();
    }

    int buf = 0;
    for (int kt = 0; kt < KT; kt++) {
        if (kt + 1 < KT) {
            const int nbuf = buf ^ 1;
            const uint32_t sA = sbase + nbuf*STAGE_B, sB = sA + A_STAGE;
            const __half* Agk = Ag + (kt+1)*BK;
            const __half* Bgk = Bg + (kt+1)*BK;
            #pragma unroll
            for (int i = 0; i < 4; i++) {
                uint32_t c = ((uint32_t)(scol + i*16)) ^ sxor;
                cpa16(sA + srow*128 + c, Agk + i*8);
                cpa16(sB + srow*128 + c, Bgk + i*8);
            }
            asm volatile("cp.async.commit_group;\n" ::);
        }

        const uint32_t aBase = sbase + buf*STAGE_B + aRow*128;
        const uint32_t bBase = sbase + buf*STAGE_B + A_STAGE + bRow*128;
        #pragma unroll
        for (int ks = 0; ks < BK/16; ks++) {
            uint32_t afr[4][4];
            const uint32_t ac = ((uint32_t)(ks*32) + aKoff) ^ fxor;
            #pragma unroll
            for (int mt = 0; mt < 4; mt++)
                ldsm4(afr[mt], aBase + mt*16*128 + ac);
            uint32_t bfr[8];
            const uint32_t bc = ((uint32_t)(ks*32) + bKoff) ^ fxor;
            ldsm4(bfr,     bBase + bc);
            ldsm4(bfr + 4, bBase + 16*128 + bc);
            #pragma unroll
            for (int mt = 0; mt < 4; mt++)
                #pragma unroll
                for (int nt = 0; nt < 4; nt++)
                    mma_f16(acc[mt][nt], afr[mt], bfr + nt*2);
        }

        asm volatile("cp.async.wait_group 0;\n" ::);
        __syncthreads();
        buf ^= 1;
    }

    float bv0[4], bv1[4];
    #pragma unroll
    for (int nt = 0; nt < 4; nt++) {
        int cl = nloc0 + wn*32 + nt*8 + qc*2;
        bv0[nt] = biasP[cl];
        bv1[nt] = biasP[cl + 1];
    }
    #pragma unroll
    for (int mt = 0; mt < 4; mt++) {
        int r0 = mb*BM + wm*64 + mt*16 + qr;
        #pragma unroll
        for (int nt = 0; nt < 4; nt++) {
            int c0 = nb*BN + wn*32 + nt*8 + qc*2;
            size_t o0 = (size_t)r0*N + c0;
            size_t o1 = o0 + (size_t)8*N;
            float v0 = acc[mt][nt][0] + bv0[nt];
            float v1 = acc[mt][nt][1] + bv1[nt];
            float v2 = acc[mt][nt][2] + bv0[nt];
            float v3 = acc[mt][nt][3] + bv1[nt];
            if (HOUT) {
                __half* C = (__half*)Cv;
                *(__half2*)(C + o0) = __floats2half2_rn(v0, v1);
                *(__half2*)(C + o1) = __floats2half2_rn(v2, v3);
            } else {
                float* C = (float*)Cv;
                if (RES) {
                    v0 += res[o0]; v1 += res[o0 + 1];
                    v2 += res[o1]; v3 += res[o1 + 1];
                }
                *(float2*)(C + o0) = make_float2(v0, v1);
                *(float2*)(C + o1) = make_float2(v2, v3);
            }
        }
    }
}

// ---------------- attention: one warp per (row, h); pointers pre-offset ----
__global__ void attn_kernel(const __half* __restrict__ q,
                            const __half* __restrict__ kv2,
                            const __half* __restrict__ kv3,
                            __half* __restrict__ attn,
                            float* __restrict__ wout) {
    int gw   = (blockIdx.x * blockDim.x + threadIdx.x) >> 5;   // row*16 + h
    int lane = threadIdx.x & 31;
    int b = gw >> 4;
    int h = gw & 15;
    size_t qoff = (size_t)b*FEAT_     + h*HDIM + lane*4;
    size_t koff = (size_t)b*(2*FEAT_) + h*HDIM + lane*4;

    uint2 qr = *(const uint2*)(q   + qoff);
    uint2 k2r = *(const uint2*)(kv2 + koff);
    uint2 k3r = *(const uint2*)(kv3 + koff);
    uint2 v2r = *(const uint2*)(kv2 + koff + FEAT_);
    uint2 v3r = *(const uint2*)(kv3 + koff + FEAT_);

    float2 qa = __half22float2(*(__half2*)&qr.x);
    float2 qb = __half22float2(*(__half2*)&qr.y);
    float2 k2a = __half22float2(*(__half2*)&k2r.x);
    float2 k2b = __half22float2(*(__half2*)&k2r.y);
    float2 k3a = __half22float2(*(__half2*)&k3r.x);
    float2 k3b = __half22float2(*(__half2*)&k3r.y);
    float2 v2a = __half22float2(*(__half2*)&v2r.x);
    float2 v2b = __half22float2(*(__half2*)&v2r.y);
    float2 v3a = __half22float2(*(__half2*)&v3r.x);
    float2 v3b = __half22float2(*(__half2*)&v3r.y);

    float s2 = qa.x*k2a.x + qa.y*k2a.y + qb.x*k2b.x + qb.y*k2b.y;
    float s3 = qa.x*k3a.x + qa.y*k3a.y + qb.x*k3b.x + qb.y*k3b.y;
    #pragma unroll
    for (int o = 16; o; o >>= 1) {
        s2 += __shfl_xor_sync(0xffffffffu, s2, o);
        s3 += __shfl_xor_sync(0xffffffffu, s3, o);
    }
    const float scale = 0.08838834764831845f;   // 1/sqrt(128)
    s2 *= scale; s3 *= scale;
    float m  = fmaxf(s2, s3);
    float e2 = expf(s2 - m), e3 = expf(s3 - m);
    float inv = 1.f / (e2 + e3);
    float w2 = e2 * inv, w3 = e3 * inv;

    __half2 p0 = __floats2half2_rn(w2*v2a.x + w3*v3a.x, w2*v2a.y + w3*v3a.y);
    __half2 p1 = __floats2half2_rn(w2*v2b.x + w3*v3b.x, w2*v2b.y + w3*v3b.y);
    uint2 ov;
    ov.x = *(uint32_t*)&p0;
    ov.y = *(uint32_t*)&p1;
    *(uint2*)(attn + qoff) = ov;

    if (lane == 0) {
        wout[(size_t)gw*2]     = w2;
        wout[(size_t)gw*2 + 1] = w3;
    }
}

// ---------------- LayerNorm: one block per row (pointers pre-offset) -------
__global__ void ln_kernel(const float* __restrict__ y,
                          const float* __restrict__ lw,
                          const float* __restrict__ lb,
                          float* __restrict__ out) {
    __shared__ float shs[8], shq[8];
    int row = blockIdx.x, t = threadIdx.x;
    const float4* yr = (const float4*)(y + (size_t)row*CURD);
    float4 a = yr[t];
    float4 b = yr[256 + t];
    float s  = a.x+a.y+a.z+a.w + b.x+b.y+b.z+b.w;
    float qq = a.x*a.x+a.y*a.y+a.z*a.z+a.w*a.w
             + b.x*b.x+b.y*b.y+b.z*b.z+b.w*b.w;
    #pragma unroll
    for (int o = 16; o; o >>= 1) {
        s  += __shfl_xor_sync(0xffffffffu, s,  o);
        qq += __shfl_xor_sync(0xffffffffu, qq, o);
    }
    int warp = t >> 5;
    if ((t & 31) == 0) { shs[warp] = s; shq[warp] = qq; }
    __syncthreads();
    float S = 0.f, Q = 0.f;
    #pragma unroll
    for (int i = 0; i < 8; i++) { S += shs[i]; Q += shq[i]; }
    float mean = S * (1.f/2048.f);
    float inv  = rsqrtf(Q * (1.f/2048.f) - mean*mean + 1e-5f);

    const float4* lw4 = (const float4*)lw;
    const float4* lb4 = (const float4*)lb;
    float4* orow = (float4*)(out + (size_t)row*CURD);
    float4 w, z, o4;
    w = lw4[t];       z = lb4[t];
    o4.x = w.x*(a.x-mean)*inv + z.x;
    o4.y = w.y*(a.y-mean)*inv + z.y;
    o4.z = w.z*(a.z-mean)*inv + z.z;
    o4.w = w.w*(a.w-mean)*inv + z.w;
    orow[t] = o4;
    w = lw4[256+t];   z = lb4[256+t];
    o4.x = w.x*(b.x-mean)*inv + z.x;
    o4.y = w.y*(b.y-mean)*inv + z.y;
    o4.z = w.z*(b.z-mean)*inv + z.z;
    o4.w = w.w*(b.w-mean)*inv + z.w;
    orow[256+t] = o4;
}

// ---------------- launch: fork/join + 2-half tail pipelining ----------------
extern "C" void kernel_launch(void* const* d_in, const int* in_sizes, int n_in,
                              void* d_out, int out_size) {
    const float* x   = (const float*)d_in[0];
    const float* v2  = (const float*)d_in[1];
    const float* v3  = (const float*)d_in[2];
    const float* Wq  = (const float*)d_in[3];
    const float* bq  = (const float*)d_in[4];
    const float* Wk2 = (const float*)d_in[5];
    const float* bk2 = (const float*)d_in[6];
    const float* Wk3 = (const float*)d_in[7];
    const float* bk3 = (const float*)d_in[8];
    const float* Wv2 = (const float*)d_in[9];
    const float* bv2 = (const float*)d_in[10];
    const float* Wv3 = (const float*)d_in[11];
    const float* bv3 = (const float*)d_in[12];
    const float* Wo  = (const float*)d_in[13];
    const float* bo  = (const float*)d_in[14];
    const float* lw  = (const float*)d_in[15];
    const float* lb  = (const float*)d_in[16];
    float* out = (float*)d_out;

    __half *xh, *v2h, *v3h, *wqh, *wk2h, *wv2h, *wk3h, *wv3h, *woh;
    __half *qb, *kv2, *kv3, *attn;
    float *yb;
    cudaGetSymbolAddress((void**)&xh,   g_xh);
    cudaGetSymbolAddress((void**)&v2h,  g_v2h);
    cudaGetSymbolAddress((void**)&v3h,  g_v3h);
    cudaGetSymbolAddress((void**)&wqh,  g_wqh);
    cudaGetSymbolAddress((void**)&wk2h, g_wk2h);
    cudaGetSymbolAddress((void**)&wv2h, g_wv2h);
    cudaGetSymbolAddress((void**)&wk3h, g_wk3h);
    cudaGetSymbolAddress((void**)&wv3h, g_wv3h);
    cudaGetSymbolAddress((void**)&woh,  g_woh);
    cudaGetSymbolAddress((void**)&qb,   g_q);
    cudaGetSymbolAddress((void**)&kv2,  g_kv2);
    cudaGetSymbolAddress((void**)&kv3,  g_kv3);
    cudaGetSymbolAddress((void**)&attn, g_att);
    cudaGetSymbolAddress((void**)&yb,   g_y);

    cudaFuncSetAttribute((const void*)gemm_f16_kernel<false,true>,
                         cudaFuncAttributeMaxDynamicSharedMemorySize, SMEM_BYTES);
    cudaFuncSetAttribute((const void*)gemm_f16_kernel<true,false>,
                         cudaFuncAttributeMaxDynamicSharedMemorySize, SMEM_BYTES);

    cudaStream_t s1, s2, s3;
    cudaStreamCreateWithFlags(&s1, cudaStreamNonBlocking);
    cudaStreamCreateWithFlags(&s2, cudaStreamNonBlocking);
    cudaStreamCreateWithFlags(&s3, cudaStreamNonBlocking);
    cudaEvent_t e0, e2a, e2b, e3a, e3b, ewq, ewo;
    cudaEventCreateWithFlags(&e0,  cudaEventDisableTiming);
    cudaEventCreateWithFlags(&e2a, cudaEventDisableTiming);
    cudaEventCreateWithFlags(&e2b, cudaEventDisableTiming);
    cudaEventCreateWithFlags(&e3a, cudaEventDisableTiming);
    cudaEventCreateWithFlags(&e3b, cudaEventDisableTiming);
    cudaEventCreateWithFlags(&ewq, cudaEventDisableTiming);
    cudaEventCreateWithFlags(&ewo, cudaEventDisableTiming);

    const int RG = 2048, RT = 256;
    dim3 blk(NTHREADS);
    const dim3 gKVh(2*FEAT_/BN, HALF_/BM);   // (32, 64) per half
    const dim3 gWOh(CURD/BN,   HALF_/BM);    // (16, 64) per half
    const size_t woff = (size_t)out_size - (size_t)B_*HEADS_*2;

    // fork
    cudaEventRecord(e0, 0);
    cudaStreamWaitEvent(s1, e0, 0);
    cudaStreamWaitEvent(s2, e0, 0);
    cudaStreamWaitEvent(s3, e0, 0);

    // --- s1: kv2 chain, split into row halves ---
    conv_h_kernel<<<RG, RT, 0, s1>>>(v2,  v2h, (long long)B_*FEAT_/4);
    conv_h_kernel<<<RG, RT, 0, s1>>>(Wk2, wk2h,(long long)FEAT_*FEAT_/4);
    conv_h_kernel<<<RG, RT, 0, s1>>>(Wv2, wv2h,(long long)FEAT_*FEAT_/4);
    gemm_f16_kernel<false,true><<<gKVh, blk, SMEM_BYTES, s1>>>(
        v2h, wk2h, wv2h, FEAT_, bk2, bv2, nullptr, kv2, 2*FEAT_, FEAT_);
    cudaEventRecord(e2a, s1);
    gemm_f16_kernel<false,true><<<gKVh, blk, SMEM_BYTES, s1>>>(
        v2h + (size_t)HALF_*FEAT_, wk2h, wv2h, FEAT_, bk2, bv2, nullptr,
        kv2 + (size_t)HALF_*2*FEAT_, 2*FEAT_, FEAT_);
    cudaEventRecord(e2b, s1);

    // --- s2: kv3 chain, split into row halves ---
    conv_h_kernel<<<RG, RT, 0, s2>>>(v3,  v3h, (long long)B_*FEAT_/4);
    conv_h_kernel<<<RG, RT, 0, s2>>>(Wk3, wk3h,(long long)FEAT_*FEAT_/4);
    conv_h_kernel<<<RG, RT, 0, s2>>>(Wv3, wv3h,(long long)FEAT_*FEAT_/4);
    gemm_f16_kernel<false,true><<<gKVh, blk, SMEM_BYTES, s2>>>(
        v3h, wk3h, wv3h, FEAT_, bk3, bv3, nullptr, kv3, 2*FEAT_, FEAT_);
    cudaEventRecord(e3a, s2);
    gemm_f16_kernel<false,true><<<gKVh, blk, SMEM_BYTES, s2>>>(
        v3h + (size_t)HALF_*FEAT_, wk3h, wv3h, FEAT_, bk3, bv3, nullptr,
        kv3 + (size_t)HALF_*2*FEAT_, 2*FEAT_, FEAT_);
    cudaEventRecord(e3b, s2);

    // --- s3: Wq then Wo conversions (off critical path) ---
    conv_h_kernel<<<RG, RT, 0, s3>>>(Wq, wqh, (long long)FEAT_*CURD/4);
    cudaEventRecord(ewq, s3);
    conv_h_kernel<<<RG, RT, 0, s3>>>(Wo, woh, (long long)CURD*FEAT_/4);
    cudaEventRecord(ewo, s3);

    // --- main: x conv -> q GEMM (full) ---
    conv_h_kernel<<<RG, RT>>>(x, xh, (long long)B_*CURD/4);
    cudaStreamWaitEvent(0, ewq, 0);
    gemm_f16_kernel<false,true><<<dim3(FEAT_/BN, B_/BM), blk, SMEM_BYTES>>>(
        xh, wqh, wqh, FEAT_, bq, bq, nullptr, qb, FEAT_, CURD);

    // --- half A tail: attn_a -> wo_a -> ln_a (overlaps kv half B GEMMs) ---
    cudaStreamWaitEvent(0, e2a, 0);
    cudaStreamWaitEvent(0, e3a, 0);
    attn_kernel<<<HALF_*HEADS_/8, 256>>>(qb, kv2, kv3, attn, out + woff);
    cudaStreamWaitEvent(0, ewo, 0);
    gemm_f16_kernel<true,false><<<gWOh, blk, SMEM_BYTES>>>(
        attn, woh, woh, CURD, bo, bo, x, yb, CURD, FEAT_);
    ln_kernel<<<HALF_, 256>>>(yb, lw, lb, out);

    // --- half B tail ---
    cudaStreamWaitEvent(0, e2b, 0);
    cudaStreamWaitEvent(0, e3b, 0);
    attn_kernel<<<HALF_*HEADS_/8, 256>>>(
        qb  + (size_t)HALF_*FEAT_,
        kv2 + (size_t)HALF_*2*FEAT_,
        kv3 + (size_t)HALF_*2*FEAT_,
        attn + (size_t)HALF_*FEAT_,
        out + woff + (size_t)HALF_*HEADS_*2);
    gemm_f16_kernel<true,false><<<gWOh, blk, SMEM_BYTES>>>(
        attn + (size_t)HALF_*FEAT_, woh, woh, CURD, bo, bo,
        x + (size_t)HALF_*CURD, yb + (size_t)HALF_*CURD, CURD, FEAT_);
    ln_kernel<<<HALF_, 256>>>(yb + (size_t)HALF_*CURD, lw, lb,
                              out + (size_t)HALF_*CURD);

    // destroy only when NOT capturing (one-time leak on the capture call;
    // no tracked device memory involved)
    cudaStreamCaptureStatus cs = cudaStreamCaptureStatusNone;
    cudaStreamIsCapturing(0, &cs);
    if (cs == cudaStreamCaptureStatusNone) {
        cudaEventDestroy(e0);  cudaEventDestroy(e2a); cudaEventDestroy(e2b);
        cudaEventDestroy(e3a); cudaEventDestroy(e3b);
        cudaEventDestroy(ewq); cudaEventDestroy(ewo);
        cudaStreamDestroy(s1); cudaStreamDestroy(s2); cudaStreamDestroy(s3);
    }
}

// round 17
// speedup vs baseline: 1.7012x; 1.1306x over previous
#include <cuda_runtime.h>
#include <cuda_fp16.h>
#include <cstdint>

#define B_    16384
#define HALF_ (B_/2)
#define CURD  2048
#define FEAT_ 2048
#define HEADS_ 16
#define HDIM  128

#define NTHREADS 512            // 16 warps, warp grid 4(M) x 4(N), warp tile 32x32
#define BM 128
#define BN 128
#define BK 64
#define A_STAGE   16384
#define STAGE_B   (2*A_STAGE)          // 32 KB
#define SMEM_BYTES (2*STAGE_B)         // 2 stages = 64 KB -> 2 CTAs/SM

// ---------------- scratch (device globals; no allocation allowed) ----------
__device__ __align__(16) __half g_xh [(size_t)B_*CURD];
__device__ __align__(16) __half g_v2h[(size_t)B_*FEAT_];
__device__ __align__(16) __half g_v3h[(size_t)B_*FEAT_];
__device__ __align__(16) __half g_wqh [(size_t)FEAT_*CURD];
__device__ __align__(16) __half g_wk2h[(size_t)FEAT_*FEAT_];
__device__ __align__(16) __half g_wv2h[(size_t)FEAT_*FEAT_];
__device__ __align__(16) __half g_wk3h[(size_t)FEAT_*FEAT_];
__device__ __align__(16) __half g_wv3h[(size_t)FEAT_*FEAT_];
__device__ __align__(16) __half g_woh [(size_t)CURD*FEAT_];
__device__ __align__(16) __half g_q  [(size_t)B_*FEAT_];
__device__ __align__(16) __half g_kv2[(size_t)B_*2*FEAT_];
__device__ __align__(16) __half g_kv3[(size_t)B_*2*FEAT_];
__device__ __align__(16) __half g_att[(size_t)B_*FEAT_];
__device__ __align__(16) float  g_y  [(size_t)B_*CURD];

// ---------------- helpers ----------------
__device__ __forceinline__ void cpa16(uint32_t s, const void* g) {
    asm volatile("cp.async.cg.shared.global [%0], [%1], 16;\n" :: "r"(s), "l"(g));
}

__device__ __forceinline__ void ldsm4(uint32_t* r, uint32_t addr) {
    asm volatile("ldmatrix.sync.aligned.m8n8.x4.shared.b16 {%0,%1,%2,%3}, [%4];"
        : "=r"(r[0]), "=r"(r[1]), "=r"(r[2]), "=r"(r[3]) : "r"(addr));
}

__device__ __forceinline__ void mma_f16(float* c, const uint32_t* a, const uint32_t* b) {
    asm volatile(
        "mma.sync.aligned.m16n8k16.row.col.f32.f16.f16.f32 "
        "{%0,%1,%2,%3}, {%4,%5,%6,%7}, {%8,%9}, {%0,%1,%2,%3};"
        : "+f"(c[0]), "+f"(c[1]), "+f"(c[2]), "+f"(c[3])
        : "r"(a[0]), "r"(a[1]), "r"(a[2]), "r"(a[3]),
          "r"(b[0]), "r"(b[1]));
}

// ---------------- fp32 -> fp16 conversion (RN) ------------------------------
__global__ void conv_h_kernel(const float* __restrict__ in,
                              __half* __restrict__ out, long long n4) {
    long long i  = blockIdx.x * (long long)blockDim.x + threadIdx.x;
    long long st = (long long)gridDim.x * blockDim.x;
    const float4* in4 = (const float4*)in;
    __half2* o2 = (__half2*)out;
    for (; i < n4; i += st) {
        float4 v = in4[i];
        o2[2*i]   = __floats2half2_rn(v.x, v.y);
        o2[2*i+1] = __floats2half2_rn(v.z, v.w);
    }
}

// ---------------- FP16 GEMM:  C = A @ W^T + bias (+res)
// CTA tile 128x128, 512 threads, warp grid 4(M) x 4(N), warp tile 32x32,
// 2 CTAs/SM (32 warps/SM). SW128 smem, ldmatrix, 2-stage cp.async.
template<bool RES, bool HOUT>
__global__ __launch_bounds__(NTHREADS, 2)
void gemm_f16_kernel(const __half* __restrict__ A,
                     const __half* __restrict__ W0,
                     const __half* __restrict__ W1,
                     int Nsplit,
                     const float* __restrict__ bias0,
                     const float* __restrict__ bias1,
                     const float* __restrict__ res,
                     void* __restrict__ Cv,
                     int N, int K) {
    extern __shared__ __align__(1024) char smem[];
    const uint32_t sbase = (uint32_t)__cvta_generic_to_shared(smem);

    const int nb = blockIdx.x, mb = blockIdx.y;
    const __half* Wp; const float* biasP; int nloc0;
    if (nb*BN < Nsplit) { Wp = W0; biasP = bias0; nloc0 = nb*BN; }
    else                { Wp = W1; biasP = bias1; nloc0 = nb*BN - Nsplit; }

    const int tid  = threadIdx.x;
    const int warp = tid >> 5, lane = tid & 31;
    const int wm = warp & 3;           // 4 M bands of 32 rows
    const int wn = warp >> 2;          // 4 N bands of 32 cols
    const int qr = lane >> 2, qc = lane & 3;

    // staging: per thread 32B of A and 32B of B per stage (512 thr x 32B = 16KB)
    const int srow = tid >> 2;                 // 0..127
    const int scol = (tid & 3) * 32;           // byte col 0/32/64/96
    const uint32_t sxor = (uint32_t)((srow & 7) << 4);
    const __half* Ag = A  + (size_t)(mb*BM + srow)*K + scol/2;
    const __half* Bg = Wp + (size_t)(nloc0 + srow)*K + scol/2;

    // ldmatrix addressing
    const int j  = lane >> 3;
    const int rr = lane & 7;
    const uint32_t fxor = (uint32_t)(rr << 4);
    const uint32_t aRow  = (uint32_t)(wm*32 + (j&1)*8 + rr);
    const uint32_t aKoff = (uint32_t)((j>>1)*16);
    const uint32_t bRow  = (uint32_t)(wn*32 + (j>>1)*8 + rr);
    const uint32_t bKoff = (uint32_t)((j&1)*16);

    float acc[2][4][4];
    #pragma unroll
    for (int i = 0; i < 2; i++)
        #pragma unroll
        for (int jn = 0; jn < 4; jn++)
            #pragma unroll
            for (int l = 0; l < 4; l++) acc[i][jn][l] = 0.f;

    const int KT = K / BK;

    // prologue: stage 0
    {
        const uint32_t sA = sbase, sB = sbase + A_STAGE;
        #pragma unroll
        for (int i = 0; i < 2; i++) {
            uint32_t c = ((uint32_t)(scol + i*16)) ^ sxor;
            cpa16(sA + srow*128 + c, Ag + i*8);
            cpa16(sB + srow*128 + c, Bg + i*8);
        }
        asm volatile("cp.async.commit_group;\n" ::);
        asm volatile("cp.async.wait_group 0;\n" ::);
        __syncthreads();
    }

    int buf = 0;
    for (int kt = 0; kt < KT; kt++) {
        if (kt + 1 < KT) {
            const int nbuf = buf ^ 1;
            const uint32_t sA = sbase + nbuf*STAGE_B, sB = sA + A_STAGE;
            const __half* Agk = Ag + (kt+1)*BK;
            const __half* Bgk = Bg + (kt+1)*BK;
            #pragma unroll
            for (int i = 0; i < 2; i++) {
                uint32_t c = ((uint32_t)(scol + i*16)) ^ sxor;
                cpa16(sA + srow*128 + c, Agk + i*8);
                cpa16(sB + srow*128 + c, Bgk + i*8);
            }
            asm volatile("cp.async.commit_group;\n" ::);
        }

        const uint32_t aBase = sbase + buf*STAGE_B + aRow*128;
        const uint32_t bBase = sbase + buf*STAGE_B + A_STAGE + bRow*128;
        #pragma unroll
        for (int ks = 0; ks < BK/16; ks++) {
            uint32_t afr[2][4];
            const uint32_t ac = ((uint32_t)(ks*32) + aKoff) ^ fxor;
            ldsm4(afr[0], aBase + ac);
            ldsm4(afr[1], aBase + 16*128 + ac);
            uint32_t bfr[8];
            const uint32_t bc = ((uint32_t)(ks*32) + bKoff) ^ fxor;
            ldsm4(bfr,     bBase + bc);              // n-subtiles 0,1
            ldsm4(bfr + 4, bBase + 16*128 + bc);     // n-subtiles 2,3
            #pragma unroll
            for (int mt = 0; mt < 2; mt++)
                #pragma unroll
                for (int nt = 0; nt < 4; nt++)
                    mma_f16(acc[mt][nt], afr[mt], bfr + nt*2);
        }

        asm volatile("cp.async.wait_group 0;\n" ::);
        __syncthreads();
        buf ^= 1;
    }

    // epilogue: bias (+residual), fp16 or fp32 stores
    float bv0[4], bv1[4];
    #pragma unroll
    for (int nt = 0; nt < 4; nt++) {
        int cl = nloc0 + wn*32 + nt*8 + qc*2;
        bv0[nt] = biasP[cl];
        bv1[nt] = biasP[cl + 1];
    }
    #pragma unroll
    for (int mt = 0; mt < 2; mt++) {
        int r0 = mb*BM + wm*32 + mt*16 + qr;
        #pragma unroll
        for (int nt = 0; nt < 4; nt++) {
            int c0 = nb*BN + wn*32 + nt*8 + qc*2;
            size_t o0 = (size_t)r0*N + c0;
            size_t o1 = o0 + (size_t)8*N;
            float v0 = acc[mt][nt][0] + bv0[nt];
            float v1 = acc[mt][nt][1] + bv1[nt];
            float v2 = acc[mt][nt][2] + bv0[nt];
            float v3 = acc[mt][nt][3] + bv1[nt];
            if (HOUT) {
                __half* C = (__half*)Cv;
                *(__half2*)(C + o0) = __floats2half2_rn(v0, v1);
                *(__half2*)(C + o1) = __floats2half2_rn(v2, v3);
            } else {
                float* C = (float*)Cv;
                if (RES) {
                    v0 += res[o0]; v1 += res[o0 + 1];
                    v2 += res[o1]; v3 += res[o1 + 1];
                }
                *(float2*)(C + o0) = make_float2(v0, v1);
                *(float2*)(C + o1) = make_float2(v2, v3);
            }
        }
    }
}

// ---------------- attention: one warp per (row, h); pointers pre-offset ----
__global__ void attn_kernel(const __half* __restrict__ q,
                            const __half* __restrict__ kv2,
                            const __half* __restrict__ kv3,
                            __half* __restrict__ attn,
                            float* __restrict__ wout) {
    int gw   = (blockIdx.x * blockDim.x + threadIdx.x) >> 5;   // row*16 + h
    int lane = threadIdx.x & 31;
    int b = gw >> 4;
    int h = gw & 15;
    size_t qoff = (size_t)b*FEAT_     + h*HDIM + lane*4;
    size_t koff = (size_t)b*(2*FEAT_) + h*HDIM + lane*4;

    uint2 qr = *(const uint2*)(q   + qoff);
    uint2 k2r = *(const uint2*)(kv2 + koff);
    uint2 k3r = *(const uint2*)(kv3 + koff);
    uint2 v2r = *(const uint2*)(kv2 + koff + FEAT_);
    uint2 v3r = *(const uint2*)(kv3 + koff + FEAT_);

    float2 qa = __half22float2(*(__half2*)&qr.x);
    float2 qb = __half22float2(*(__half2*)&qr.y);
    float2 k2a = __half22float2(*(__half2*)&k2r.x);
    float2 k2b = __half22float2(*(__half2*)&k2r.y);
    float2 k3a = __half22float2(*(__half2*)&k3r.x);
    float2 k3b = __half22float2(*(__half2*)&k3r.y);
    float2 v2a = __half22float2(*(__half2*)&v2r.x);
    float2 v2b = __half22float2(*(__half2*)&v2r.y);
    float2 v3a = __half22float2(*(__half2*)&v3r.x);
    float2 v3b = __half22float2(*(__half2*)&v3r.y);

    float s2 = qa.x*k2a.x + qa.y*k2a.y + qb.x*k2b.x + qb.y*k2b.y;
    float s3 = qa.x*k3a.x + qa.y*k3a.y + qb.x*k3b.x + qb.y*k3b.y;
    #pragma unroll
    for (int o = 16; o; o >>= 1) {
        s2 += __shfl_xor_sync(0xffffffffu, s2, o);
        s3 += __shfl_xor_sync(0xffffffffu, s3, o);
    }
    const float scale = 0.08838834764831845f;   // 1/sqrt(128)
    s2 *= scale; s3 *= scale;
    float m  = fmaxf(s2, s3);
    float e2 = expf(s2 - m), e3 = expf(s3 - m);
    float inv = 1.f / (e2 + e3);
    float w2 = e2 * inv, w3 = e3 * inv;

    __half2 p0 = __floats2half2_rn(w2*v2a.x + w3*v3a.x, w2*v2a.y + w3*v3a.y);
    __half2 p1 = __floats2half2_rn(w2*v2b.x + w3*v3b.x, w2*v2b.y + w3*v3b.y);
    uint2 ov;
    ov.x = *(uint32_t*)&p0;
    ov.y = *(uint32_t*)&p1;
    *(uint2*)(attn + qoff) = ov;

    if (lane == 0) {
        wout[(size_t)gw*2]     = w2;
        wout[(size_t)gw*2 + 1] = w3;
    }
}

// ---------------- LayerNorm: one block per row (pointers pre-offset) -------
__global__ void ln_kernel(const float* __restrict__ y,
                          const float* __restrict__ lw,
                          const float* __restrict__ lb,
                          float* __restrict__ out) {
    __shared__ float shs[8], shq[8];
    int row = blockIdx.x, t = threadIdx.x;
    const float4* yr = (const float4*)(y + (size_t)row*CURD);
    float4 a = yr[t];
    float4 b = yr[256 + t];
    float s  = a.x+a.y+a.z+a.w + b.x+b.y+b.z+b.w;
    float qq = a.x*a.x+a.y*a.y+a.z*a.z+a.w*a.w
             + b.x*b.x+b.y*b.y+b.z*b.z+b.w*b.w;
    #pragma unroll
    for (int o = 16; o; o >>= 1) {
        s  += __shfl_xor_sync(0xffffffffu, s,  o);
        qq += __shfl_xor_sync(0xffffffffu, qq, o);
    }
    int warp = t >> 5;
    if ((t & 31) == 0) { shs[warp] = s; shq[warp] = qq; }
    __syncthreads();
    float S = 0.f, Q = 0.f;
    #pragma unroll
    for (int i = 0; i < 8; i++) { S += shs[i]; Q += shq[i]; }
    float mean = S * (1.f/2048.f);
    float inv  = rsqrtf(Q * (1.f/2048.f) - mean*mean + 1e-5f);

    const float4* lw4 = (const float4*)lw;
    const float4* lb4 = (const float4*)lb;
    float4* orow = (float4*)(out + (size_t)row*CURD);
    float4 w, z, o4;
    w = lw4[t];       z = lb4[t];
    o4.x = w.x*(a.x-mean)*inv + z.x;
    o4.y = w.y*(a.y-mean)*inv + z.y;
    o4.z = w.z*(a.z-mean)*inv + z.z;
    o4.w = w.w*(a.w-mean)*inv + z.w;
    orow[t] = o4;
    w = lw4[256+t];   z = lb4[256+t];
    o4.x = w.x*(b.x-mean)*inv + z.x;
    o4.y = w.y*(b.y-mean)*inv + z.y;
    o4.z = w.z*(b.z-mean)*inv + z.z;
    o4.w = w.w*(b.w-mean)*inv + z.w;
    orow[256+t] = o4;
}

// ---------------- launch: fork/join + 2-half tail pipelining ----------------
extern "C" void kernel_launch(void* const* d_in, const int* in_sizes, int n_in,
                              void* d_out, int out_size) {
    const float* x   = (const float*)d_in[0];
    const float* v2  = (const float*)d_in[1];
    const float* v3  = (const float*)d_in[2];
    const float* Wq  = (const float*)d_in[3];
    const float* bq  = (const float*)d_in[4];
    const float* Wk2 = (const float*)d_in[5];
    const float* bk2 = (const float*)d_in[6];
    const float* Wk3 = (const float*)d_in[7];
    const float* bk3 = (const float*)d_in[8];
    const float* Wv2 = (const float*)d_in[9];
    const float* bv2 = (const float*)d_in[10];
    const float* Wv3 = (const float*)d_in[11];
    const float* bv3 = (const float*)d_in[12];
    const float* Wo  = (const float*)d_in[13];
    const float* bo  = (const float*)d_in[14];
    const float* lw  = (const float*)d_in[15];
    const float* lb  = (const float*)d_in[16];
    float* out = (float*)d_out;

    __half *xh, *v2h, *v3h, *wqh, *wk2h, *wv2h, *wk3h, *wv3h, *woh;
    __half *qb, *kv2, *kv3, *attn;
    float *yb;
    cudaGetSymbolAddress((void**)&xh,   g_xh);
    cudaGetSymbolAddress((void**)&v2h,  g_v2h);
    cudaGetSymbolAddress((void**)&v3h,  g_v3h);
    cudaGetSymbolAddress((void**)&wqh,  g_wqh);
    cudaGetSymbolAddress((void**)&wk2h, g_wk2h);
    cudaGetSymbolAddress((void**)&wv2h, g_wv2h);
    cudaGetSymbolAddress((void**)&wk3h, g_wk3h);
    cudaGetSymbolAddress((void**)&wv3h, g_wv3h);
    cudaGetSymbolAddress((void**)&woh,  g_woh);
    cudaGetSymbolAddress((void**)&qb,   g_q);
    cudaGetSymbolAddress((void**)&kv2,  g_kv2);
    cudaGetSymbolAddress((void**)&kv3,  g_kv3);
    cudaGetSymbolAddress((void**)&attn, g_att);
    cudaGetSymbolAddress((void**)&yb,   g_y);

    cudaFuncSetAttribute((const void*)gemm_f16_kernel<false,true>,
                         cudaFuncAttributeMaxDynamicSharedMemorySize, SMEM_BYTES);
    cudaFuncSetAttribute((const void*)gemm_f16_kernel<true,false>,
                         cudaFuncAttributeMaxDynamicSharedMemorySize, SMEM_BYTES);

    cudaStream_t s1, s2, s3;
    cudaStreamCreateWithFlags(&s1, cudaStreamNonBlocking);
    cudaStreamCreateWithFlags(&s2, cudaStreamNonBlocking);
    cudaStreamCreateWithFlags(&s3, cudaStreamNonBlocking);
    cudaEvent_t e0, e2a, e2b, e3a, e3b, ewq, ewo;
    cudaEventCreateWithFlags(&e0,  cudaEventDisableTiming);
    cudaEventCreateWithFlags(&e2a, cudaEventDisableTiming);
    cudaEventCreateWithFlags(&e2b, cudaEventDisableTiming);
    cudaEventCreateWithFlags(&e3a, cudaEventDisableTiming);
    cudaEventCreateWithFlags(&e3b, cudaEventDisableTiming);
    cudaEventCreateWithFlags(&ewq, cudaEventDisableTiming);
    cudaEventCreateWithFlags(&ewo, cudaEventDisableTiming);

    const int RG = 2048, RT = 256;
    dim3 blk(NTHREADS);
    const dim3 gKVh(2*FEAT_/BN, HALF_/BM);   // (32, 64) per half
    const dim3 gWOh(CURD/BN,   HALF_/BM);    // (16, 64) per half
    const size_t woff = (size_t)out_size - (size_t)B_*HEADS_*2;

    // fork
    cudaEventRecord(e0, 0);
    cudaStreamWaitEvent(s1, e0, 0);
    cudaStreamWaitEvent(s2, e0, 0);
    cudaStreamWaitEvent(s3, e0, 0);

    // --- s1: kv2 chain, split into row halves ---
    conv_h_kernel<<<RG, RT, 0, s1>>>(v2,  v2h, (long long)B_*FEAT_/4);
    conv_h_kernel<<<RG, RT, 0, s1>>>(Wk2, wk2h,(long long)FEAT_*FEAT_/4);
    conv_h_kernel<<<RG, RT, 0, s1>>>(Wv2, wv2h,(long long)FEAT_*FEAT_/4);
    gemm_f16_kernel<false,true><<<gKVh, blk, SMEM_BYTES, s1>>>(
        v2h, wk2h, wv2h, FEAT_, bk2, bv2, nullptr, kv2, 2*FEAT_, FEAT_);
    cudaEventRecord(e2a, s1);
    gemm_f16_kernel<false,true><<<gKVh, blk, SMEM_BYTES, s1>>>(
        v2h + (size_t)HALF_*FEAT_, wk2h, wv2h, FEAT_, bk2, bv2, nullptr,
        kv2 + (size_t)HALF_*2*FEAT_, 2*FEAT_, FEAT_);
    cudaEventRecord(e2b, s1);

    // --- s2: kv3 chain, split into row halves ---
    conv_h_kernel<<<RG, RT, 0, s2>>>(v3,  v3h, (long long)B_*FEAT_/4);
    conv_h_kernel<<<RG, RT, 0, s2>>>(Wk3, wk3h,(long long)FEAT_*FEAT_/4);
    conv_h_kernel<<<RG, RT, 0, s2>>>(Wv3, wv3h,(long long)FEAT_*FEAT_/4);
    gemm_f16_kernel<false,true><<<gKVh, blk, SMEM_BYTES, s2>>>(
        v3h, wk3h, wv3h, FEAT_, bk3, bv3, nullptr, kv3, 2*FEAT_, FEAT_);
    cudaEventRecord(e3a, s2);
    gemm_f16_kernel<false,true><<<gKVh, blk, SMEM_BYTES, s2>>>(
        v3h + (size_t)HALF_*FEAT_, wk3h, wv3h, FEAT_, bk3, bv3, nullptr,
        kv3 + (size_t)HALF_*2*FEAT_, 2*FEAT_, FEAT_);
    cudaEventRecord(e3b, s2);

    // --- s3: Wq then Wo conversions (off critical path) ---
    conv_h_kernel<<<RG, RT, 0, s3>>>(Wq, wqh, (long long)FEAT_*CURD/4);
    cudaEventRecord(ewq, s3);
    conv_h_kernel<<<RG, RT, 0, s3>>>(Wo, woh, (long long)CURD*FEAT_/4);
    cudaEventRecord(ewo, s3);

    // --- main: x conv -> q GEMM (full) ---
    conv_h_kernel<<<RG, RT>>>(x, xh, (long long)B_*CURD/4);
    cudaStreamWaitEvent(0, ewq, 0);
    gemm_f16_kernel<false,true><<<dim3(FEAT_/BN, B_/BM), blk, SMEM_BYTES>>>(
        xh, wqh, wqh, FEAT_, bq, bq, nullptr, qb, FEAT_, CURD);

    // --- half A tail: attn_a -> wo_a -> ln_a (overlaps kv half B GEMMs) ---
    cudaStreamWaitEvent(0, e2a, 0);
    cudaStreamWaitEvent(0, e3a, 0);
    attn_kernel<<<HALF_*HEADS_/8, 256>>>(qb, kv2, kv3, attn, out + woff);
    cudaStreamWaitEvent(0, ewo, 0);
    gemm_f16_kernel<true,false><<<gWOh, blk, SMEM_BYTES>>>(
        attn, woh, woh, CURD, bo, bo, x, yb, CURD, FEAT_);
    ln_kernel<<<HALF_, 256>>>(yb, lw, lb, out);

    // --- half B tail ---
    cudaStreamWaitEvent(0, e2b, 0);
    cudaStreamWaitEvent(0, e3b, 0);
    attn_kernel<<<HALF_*HEADS_/8, 256>>>(
        qb  + (size_t)HALF_*FEAT_,
        kv2 + (size_t)HALF_*2*FEAT_,
        kv3 + (size_t)HALF_*2*FEAT_,
        attn + (size_t)HALF_*FEAT_,
        out + woff + (size_t)HALF_*HEADS_*2);
    gemm_f16_kernel<true,false><<<gWOh, blk, SMEM_BYTES>>>(
        attn + (size_t)HALF_*FEAT_, woh, woh, CURD, bo, bo,
        x + (size_t)HALF_*CURD, yb + (size_t)HALF_*CURD, CURD, FEAT_);
    ln_kernel<<<HALF_, 256>>>(yb + (size_t)HALF_*CURD, lw, lb,
                              out + (size_t)HALF_*CURD);

    // destroy only when NOT capturing
    cudaStreamCaptureStatus cs = cudaStreamCaptureStatusNone;
    cudaStreamIsCapturing(0, &cs);
    if (cs == cudaStreamCaptureStatusNone) {
        cudaEventDestroy(e0);  cudaEventDestroy(e2a); cudaEventDestroy(e2b);
        cudaEventDestroy(e3a); cudaEventDestroy(e3b);
        cudaEventDestroy(ewq); cudaEventDestroy(ewo);
        cudaStreamDestroy(s1); cudaStreamDestroy(s2); cudaStreamDestroy(s3);
    }
}